// round 13
// baseline (speedup 1.0000x reference)
#include <cuda_runtime.h>
#include <cuda_fp16.h>
#include <cstdint>

// WQuantLinear factorized, FUSED quant-in-GEMM (prepW eliminated):
//   q = clip(round(w*(1/scale))+zero, 0, 15)  computed inside the GEMM pipeline
//   out = scale[n]*(sum_k h(a)*q) - scale[n]*zero[n]*S[m] + bias[n]
// Pipeline per k-tile: cp.async raw fp32 W + fp16 A -> cooperative quant of tile
// kt+1 into u8-permuted smem -> fragment load (LDSM A, LDS.32+PRMT-expand B) -> HMMA.
// prepA (tiny) still converts A->fp16 and computes rowsums S.

constexpr int M_TOTAL = 256;
constexpr int N_TOTAL = 11008;
constexpr int K_TOTAL = 4096;

constexpr int BM = 128;
constexpr int BN = 64;
constexpr int BK = 32;
constexpr int NT = K_TOTAL / BK;       // 128
constexpr int GEMM_THREADS = 128;      // 4 warps: 2(m) x 2(n), 64x32 warp tiles
constexpr int STAGES = 4;

constexpr int ROW_A = 80;              // A: 64B fp16 + 16B pad (LDSM conflict-free)
constexpr int ROW_W = 160;             // raw W: 128B fp32 + 32B pad (40 words -> conflict-free LDS.128)
constexpr int ROW_Q = 48;              // Bq: 32B u8 + 16B pad
constexpr int A_STAGE_B = BM * ROW_A;          // 10240
constexpr int W_STAGE_B = BN * ROW_W;          // 10240
constexpr int Q_STAGE_B = BN * ROW_Q;          // 3072
constexpr int STAGE_B = A_STAGE_B + W_STAGE_B + Q_STAGE_B; // 23552
constexpr int SMEM_BYTES = STAGES * STAGE_B;   // 94208 (2 CTAs/SM)

// ---- device scratch ----
__device__ __half g_Ah[M_TOTAL * K_TOTAL];
__device__ float  g_S[M_TOTAL];

__device__ __forceinline__ void mma_f16(float c[4], const uint32_t a[4], const uint32_t b[2]) {
    asm volatile(
        "mma.sync.aligned.m16n8k16.row.col.f32.f16.f16.f32 "
        "{%0,%1,%2,%3}, {%4,%5,%6,%7}, {%8,%9}, {%0,%1,%2,%3};"
        : "+f"(c[0]), "+f"(c[1]), "+f"(c[2]), "+f"(c[3])
        : "r"(a[0]), "r"(a[1]), "r"(a[2]), "r"(a[3]), "r"(b[0]), "r"(b[1]));
}
__device__ __forceinline__ void ldsm4(uint32_t r[4], uint32_t addr) {
    asm volatile("ldmatrix.sync.aligned.m8n8.x4.shared.b16 {%0,%1,%2,%3}, [%4];"
                 : "=r"(r[0]), "=r"(r[1]), "=r"(r[2]), "=r"(r[3]) : "r"(addr));
}
__device__ __forceinline__ uint32_t lds32(uint32_t addr) {
    uint32_t v;
    asm volatile("ld.shared.b32 %0, [%1];" : "=r"(v) : "r"(addr));
    return v;
}
__device__ __forceinline__ float4 lds128f(uint32_t addr) {
    float4 v;
    asm volatile("ld.shared.v4.f32 {%0,%1,%2,%3}, [%4];"
                 : "=f"(v.x), "=f"(v.y), "=f"(v.z), "=f"(v.w) : "r"(addr));
    return v;
}
__device__ __forceinline__ void sts64(uint32_t addr, uint32_t a, uint32_t b) {
    asm volatile("st.shared.v2.b32 [%0], {%1,%2};" :: "r"(addr), "r"(a), "r"(b) : "memory");
}
__device__ __forceinline__ void cpasync16(uint32_t dst, const void* src) {
    asm volatile("cp.async.cg.shared.global [%0], [%1], 16;" :: "r"(dst), "l"(src) : "memory");
}
__device__ __forceinline__ uint32_t s2u(const void* p) {
    uint32_t a;
    asm("{ .reg .u64 t; cvta.to.shared.u64 t, %1; cvt.u32.u64 %0, t; }" : "=r"(a) : "l"(p));
    return a;
}
// qd bytes = [q(2t), q(2t+1), q(2t+8), q(2t+9)] -> exact fp16 pair regs
__device__ __forceinline__ void expand_q(uint32_t qd, uint32_t b[2]) {
    uint32_t p0, p1;
    asm("prmt.b32 %0, %1, %2, 0x4140;" : "=r"(p0) : "r"(qd), "r"(0x64646464u));
    asm("prmt.b32 %0, %1, %2, 0x4342;" : "=r"(p1) : "r"(qd), "r"(0x64646464u));
    asm("sub.rn.f16x2 %0, %1, %2;" : "=r"(b[0]) : "r"(p0), "r"(0x64006400u));
    asm("sub.rn.f16x2 %0, %1, %2;" : "=r"(b[1]) : "r"(p1), "r"(0x64006400u));
}
__device__ __forceinline__ uint32_t quant1(float w, float r, float z) {
    return (uint32_t)fminf(fmaxf(rintf(__fmul_rn(w, r)) + z, 0.0f), 15.0f);
}

// ---------------- prepA: A -> fp16 + rowsums ----------------
__global__ __launch_bounds__(128) void prepA_kernel(const float* __restrict__ A) {
    const int row = blockIdx.x;
    const int tid = threadIdx.x;
    const float* src = A + (size_t)row * K_TOTAL;
    __half* dst = g_Ah + (size_t)row * K_TOTAL;
    float s = 0.0f;
#pragma unroll
    for (int i = 0; i < K_TOTAL / (128 * 4); i++) {
        float4 v = *(const float4*)(src + (i * 128 + tid) * 4);
        __half h0 = __float2half_rn(v.x), h1 = __float2half_rn(v.y);
        __half h2 = __float2half_rn(v.z), h3 = __float2half_rn(v.w);
        __half2 p0 = __halves2half2(h0, h1), p1 = __halves2half2(h2, h3);
        *(uint2*)(dst + (i * 128 + tid) * 4) = make_uint2(*(uint32_t*)&p0, *(uint32_t*)&p1);
        s += __half2float(h0) + __half2float(h1) + __half2float(h2) + __half2float(h3);
    }
#pragma unroll
    for (int o = 16; o > 0; o >>= 1) s += __shfl_xor_sync(0xffffffffu, s, o);
    __shared__ float ws[4];
    if ((tid & 31) == 0) ws[tid >> 5] = s;
    __syncthreads();
    if (tid == 0) g_S[row] = ws[0] + ws[1] + ws[2] + ws[3];
}

// ---------------- fused GEMM ----------------
__global__ __launch_bounds__(GEMM_THREADS, 2)
void wq_gemm_kernel(const float* __restrict__ W,
                    const float* __restrict__ bias,
                    const float* __restrict__ scale,
                    const float* __restrict__ zero,
                    float* __restrict__ out)
{
    extern __shared__ char smem[];
    const uint32_t sb = s2u(smem);
    const int tid  = threadIdx.x;
    const int wid  = tid >> 5;
    const int lane = tid & 31;
    const int gid  = lane >> 2;
    const int tig  = lane & 3;
    const int wm   = wid & 1;        // 2 m-slabs of 64
    const int wn   = wid >> 1;       // 2 n-slabs of 32
    const int bn0 = blockIdx.x * BN;
    const int bm0 = blockIdx.y * BM;

    const __half* gA = g_Ah + (size_t)bm0 * K_TOTAL;
    const float*  gW = W + (size_t)bn0 * K_TOTAL;

    // staging maps
    const int a_row = tid >> 2;      // +32j, j<4
    const int a_c16 = tid & 3;
    const int w_row = tid >> 3;      // +16j, j<4 -> rows 0..63
    const int w_c16 = tid & 7;

    // quant task map: 2 tasks/thread; task = tid + 128*j
    //   row = task>>2 (0..63), g = (task>>1)&1, h = task&1
    const int q_row0 = tid >> 2;           // j=0 -> rows 0..31
    const int q_row1 = 32 + (tid >> 2);    // j=1 -> rows 32..63
    const int q_g = (tid >> 1) & 1;
    const int q_h = tid & 1;
    const float r0 = __fdiv_rn(1.0f, scale[bn0 + q_row0]);
    const float z0 = zero[bn0 + q_row0];
    const float r1 = __fdiv_rn(1.0f, scale[bn0 + q_row1]);
    const float z1 = zero[bn0 + q_row1];
    // word offset of quad0 within raw W row: k = g*16 + h*4
    const uint32_t q_koff = (uint32_t)((q_g * 16 + q_h * 4) * 4);   // bytes
    const uint32_t q_dst_off = (uint32_t)(q_g * 16 + q_h * 8);      // bytes in Bq row

    auto stage_tile = [&](int kt) {
        const int s = kt & (STAGES - 1);
        const uint32_t as = sb + s * STAGE_B;
        const uint32_t wsm = as + A_STAGE_B;
        const int k0 = kt * BK;
#pragma unroll
        for (int j = 0; j < 4; j++) {
            const int row = a_row + 32 * j;
            cpasync16(as + row * ROW_A + a_c16 * 16,
                      gA + (size_t)row * K_TOTAL + k0 + a_c16 * 8);
        }
#pragma unroll
        for (int j = 0; j < 4; j++) {
            const int row = w_row + 16 * j;
            cpasync16(wsm + row * ROW_W + w_c16 * 16,
                      gW + (size_t)row * K_TOTAL + k0 + w_c16 * 4);
        }
        asm volatile("cp.async.commit_group;" ::: "memory");
    };

    // quantize tile (stage s): raw fp32 W[s] -> permuted u8 Bq[s]
    auto quant_tile = [&](int s) {
        const uint32_t wsm = sb + s * STAGE_B + A_STAGE_B;
        const uint32_t qsm = wsm + W_STAGE_B;
#pragma unroll
        for (int j = 0; j < 2; j++) {
            const int row = j ? q_row1 : q_row0;
            const float rr = j ? r1 : r0;
            const float zz = j ? z1 : z0;
            const uint32_t base = wsm + row * ROW_W + q_koff;
            float4 qa = lds128f(base);        // k .. k+3
            float4 qb = lds128f(base + 32);   // k+8 .. k+11
            uint32_t i0 = quant1(qa.x, rr, zz), i1 = quant1(qa.y, rr, zz);
            uint32_t i2 = quant1(qa.z, rr, zz), i3 = quant1(qa.w, rr, zz);
            uint32_t i8 = quant1(qb.x, rr, zz), i9 = quant1(qb.y, rr, zz);
            uint32_t iA = quant1(qb.z, rr, zz), iB = quant1(qb.w, rr, zz);
            uint32_t d0 = i0 | (i1 << 8) | (i8 << 16) | (i9 << 24);
            uint32_t d1 = i2 | (i3 << 8) | (iA << 16) | (iB << 24);
            sts64(qsm + row * ROW_Q + q_dst_off, d0, d1);
        }
    };

    stage_tile(0);
    stage_tile(1);
    stage_tile(2);

    // fragment offsets
    const uint32_t a_frag = (uint32_t)((wm * 64 + (lane & 15)) * ROW_A + (lane >> 4) * 16);
    const uint32_t b_off  = (uint32_t)((wn * 32 + gid) * ROW_Q + tig * 4);

    float acc[4][4][4];
#pragma unroll
    for (int mt = 0; mt < 4; mt++)
#pragma unroll
        for (int nt = 0; nt < 4; nt++)
#pragma unroll
            for (int i = 0; i < 4; i++) acc[mt][nt][i] = 0.0f;

    // prologue: tiles 0,1 resident -> quant Bq[0]
    asm volatile("cp.async.wait_group 1;" ::: "memory");
    __syncthreads();
    quant_tile(0);

    for (int kt = 0; kt < NT; kt++) {
        const int s = kt & (STAGES - 1);
        const uint32_t as = sb + s * STAGE_B;
        const uint32_t qs = as + A_STAGE_B + W_STAGE_B;

        // RESIDENCY: tiles <= kt+1 complete after this wait (quant needs Wraw[kt+1]).
        if (kt + 3 <= NT) {
            asm volatile("cp.async.wait_group 1;" ::: "memory");
        } else {
            asm volatile("cp.async.wait_group 0;" ::: "memory");
        }
        __syncthreads();   // orders: prev-iter quant STS -> this-iter frag LDS; arrivals visible

        if (kt + 3 < NT) stage_tile(kt + 3);
        if (kt + 1 < NT) quant_tile((kt + 1) & (STAGES - 1));

#pragma unroll
        for (int ks = 0; ks < 2; ks++) {
            uint32_t af[4][4];
            uint32_t qd[4];
#pragma unroll
            for (int mt = 0; mt < 4; mt++)
                ldsm4(af[mt], as + a_frag + mt * (16 * ROW_A) + ks * 32);
#pragma unroll
            for (int nt = 0; nt < 4; nt++)
                qd[nt] = lds32(qs + b_off + nt * (8 * ROW_Q) + ks * 16);
#pragma unroll
            for (int nt = 0; nt < 4; nt++) {
                uint32_t bq[2];
                expand_q(qd[nt], bq);
#pragma unroll
                for (int mt = 0; mt < 4; mt++)
                    mma_f16(acc[mt][nt], af[mt], bq);
            }
        }
    }

    // Epilogue: out = scale*acc - scale*zero*S + bias
    float Sm[4][2];
#pragma unroll
    for (int mt = 0; mt < 4; mt++) {
        Sm[mt][0] = g_S[bm0 + wm * 64 + mt * 16 + gid];
        Sm[mt][1] = g_S[bm0 + wm * 64 + mt * 16 + gid + 8];
    }
#pragma unroll
    for (int nt = 0; nt < 4; nt++) {
        const int col = bn0 + wn * 32 + nt * 8 + tig * 2;
        const float2 sc = *(const float2*)(scale + col);
        const float2 zr = *(const float2*)(zero + col);
        const float2 bv = *(const float2*)(bias + col);
        const float sz0 = sc.x * zr.x, sz1 = sc.y * zr.y;
#pragma unroll
        for (int mt = 0; mt < 4; mt++) {
            const int row = bm0 + wm * 64 + mt * 16 + gid;
            float2 v0, v1;
            v0.x = sc.x * acc[mt][nt][0] - sz0 * Sm[mt][0] + bv.x;
            v0.y = sc.y * acc[mt][nt][1] - sz1 * Sm[mt][0] + bv.y;
            v1.x = sc.x * acc[mt][nt][2] - sz0 * Sm[mt][1] + bv.x;
            v1.y = sc.y * acc[mt][nt][3] - sz1 * Sm[mt][1] + bv.y;
            *(float2*)(out + (size_t)row * N_TOTAL + col) = v0;
            *(float2*)(out + (size_t)(row + 8) * N_TOTAL + col) = v1;
        }
    }
}

extern "C" void kernel_launch(void* const* d_in, const int* in_sizes, int n_in,
                              void* d_out, int out_size) {
    const float* input  = (const float*)d_in[0];
    const float* weight = (const float*)d_in[1];
    const float* bias   = (const float*)d_in[2];
    const float* scale  = (const float*)d_in[3];
    const float* zero   = (const float*)d_in[4];
    float* out = (float*)d_out;

    prepA_kernel<<<M_TOTAL, 128>>>(input);

    static bool attr_set = false;
    if (!attr_set) {
        cudaFuncSetAttribute(wq_gemm_kernel, cudaFuncAttributeMaxDynamicSharedMemorySize, SMEM_BYTES);
        attr_set = true;
    }
    dim3 grid(N_TOTAL / BN, M_TOTAL / BM);
    wq_gemm_kernel<<<grid, GEMM_THREADS, SMEM_BYTES>>>(weight, bias, scale, zero, out);
}

// round 14
// speedup vs baseline: 1.0005x; 1.0005x over previous
#include <cuda_runtime.h>
#include <cuda_fp16.h>
#include <cstdint>

// WQuantLinear factorized, FUSED quant-in-GEMM (prepW eliminated):
//   q = clip(round(w*(1/scale))+zero, 0, 15)  computed inside the GEMM pipeline
//   out = scale[n]*(sum_k h(a)*q) - scale[n]*zero[n]*S[m] + bias[n]
// Pipeline per k-tile: cp.async raw fp32 W + fp16 A -> cooperative quant of tile
// kt+1 into u8-permuted smem -> fragment load (LDSM A, LDS.32+PRMT-expand B) -> HMMA.
// prepA (tiny) still converts A->fp16 and computes rowsums S.

constexpr int M_TOTAL = 256;
constexpr int N_TOTAL = 11008;
constexpr int K_TOTAL = 4096;

constexpr int BM = 128;
constexpr int BN = 64;
constexpr int BK = 32;
constexpr int NT = K_TOTAL / BK;       // 128
constexpr int GEMM_THREADS = 128;      // 4 warps: 2(m) x 2(n), 64x32 warp tiles
constexpr int STAGES = 4;

constexpr int ROW_A = 80;              // A: 64B fp16 + 16B pad (LDSM conflict-free)
constexpr int ROW_W = 160;             // raw W: 128B fp32 + 32B pad (40 words -> conflict-free LDS.128)
constexpr int ROW_Q = 48;              // Bq: 32B u8 + 16B pad
constexpr int A_STAGE_B = BM * ROW_A;          // 10240
constexpr int W_STAGE_B = BN * ROW_W;          // 10240
constexpr int Q_STAGE_B = BN * ROW_Q;          // 3072
constexpr int STAGE_B = A_STAGE_B + W_STAGE_B + Q_STAGE_B; // 23552
constexpr int SMEM_BYTES = STAGES * STAGE_B;   // 94208 (2 CTAs/SM)

// ---- device scratch ----
__device__ __half g_Ah[M_TOTAL * K_TOTAL];
__device__ float  g_S[M_TOTAL];

__device__ __forceinline__ void mma_f16(float c[4], const uint32_t a[4], const uint32_t b[2]) {
    asm volatile(
        "mma.sync.aligned.m16n8k16.row.col.f32.f16.f16.f32 "
        "{%0,%1,%2,%3}, {%4,%5,%6,%7}, {%8,%9}, {%0,%1,%2,%3};"
        : "+f"(c[0]), "+f"(c[1]), "+f"(c[2]), "+f"(c[3])
        : "r"(a[0]), "r"(a[1]), "r"(a[2]), "r"(a[3]), "r"(b[0]), "r"(b[1]));
}
__device__ __forceinline__ void ldsm4(uint32_t r[4], uint32_t addr) {
    asm volatile("ldmatrix.sync.aligned.m8n8.x4.shared.b16 {%0,%1,%2,%3}, [%4];"
                 : "=r"(r[0]), "=r"(r[1]), "=r"(r[2]), "=r"(r[3]) : "r"(addr));
}
__device__ __forceinline__ uint32_t lds32(uint32_t addr) {
    uint32_t v;
    asm volatile("ld.shared.b32 %0, [%1];" : "=r"(v) : "r"(addr));
    return v;
}
__device__ __forceinline__ float4 lds128f(uint32_t addr) {
    float4 v;
    asm volatile("ld.shared.v4.f32 {%0,%1,%2,%3}, [%4];"
                 : "=f"(v.x), "=f"(v.y), "=f"(v.z), "=f"(v.w) : "r"(addr));
    return v;
}
__device__ __forceinline__ void sts64(uint32_t addr, uint32_t a, uint32_t b) {
    asm volatile("st.shared.v2.b32 [%0], {%1,%2};" :: "r"(addr), "r"(a), "r"(b) : "memory");
}
__device__ __forceinline__ void cpasync16(uint32_t dst, const void* src) {
    asm volatile("cp.async.cg.shared.global [%0], [%1], 16;" :: "r"(dst), "l"(src) : "memory");
}
__device__ __forceinline__ uint32_t s2u(const void* p) {
    uint32_t a;
    asm("{ .reg .u64 t; cvta.to.shared.u64 t, %1; cvt.u32.u64 %0, t; }" : "=r"(a) : "l"(p));
    return a;
}
// qd bytes = [q(2t), q(2t+1), q(2t+8), q(2t+9)] -> exact fp16 pair regs
__device__ __forceinline__ void expand_q(uint32_t qd, uint32_t b[2]) {
    uint32_t p0, p1;
    asm("prmt.b32 %0, %1, %2, 0x4140;" : "=r"(p0) : "r"(qd), "r"(0x64646464u));
    asm("prmt.b32 %0, %1, %2, 0x4342;" : "=r"(p1) : "r"(qd), "r"(0x64646464u));
    asm("sub.rn.f16x2 %0, %1, %2;" : "=r"(b[0]) : "r"(p0), "r"(0x64006400u));
    asm("sub.rn.f16x2 %0, %1, %2;" : "=r"(b[1]) : "r"(p1), "r"(0x64006400u));
}
__device__ __forceinline__ uint32_t quant1(float w, float r, float z) {
    return (uint32_t)fminf(fmaxf(rintf(__fmul_rn(w, r)) + z, 0.0f), 15.0f);
}

// ---------------- prepA: A -> fp16 + rowsums ----------------
__global__ __launch_bounds__(128) void prepA_kernel(const float* __restrict__ A) {
    const int row = blockIdx.x;
    const int tid = threadIdx.x;
    const float* src = A + (size_t)row * K_TOTAL;
    __half* dst = g_Ah + (size_t)row * K_TOTAL;
    float s = 0.0f;
#pragma unroll
    for (int i = 0; i < K_TOTAL / (128 * 4); i++) {
        float4 v = *(const float4*)(src + (i * 128 + tid) * 4);
        __half h0 = __float2half_rn(v.x), h1 = __float2half_rn(v.y);
        __half h2 = __float2half_rn(v.z), h3 = __float2half_rn(v.w);
        __half2 p0 = __halves2half2(h0, h1), p1 = __halves2half2(h2, h3);
        *(uint2*)(dst + (i * 128 + tid) * 4) = make_uint2(*(uint32_t*)&p0, *(uint32_t*)&p1);
        s += __half2float(h0) + __half2float(h1) + __half2float(h2) + __half2float(h3);
    }
#pragma unroll
    for (int o = 16; o > 0; o >>= 1) s += __shfl_xor_sync(0xffffffffu, s, o);
    __shared__ float ws[4];
    if ((tid & 31) == 0) ws[tid >> 5] = s;
    __syncthreads();
    if (tid == 0) g_S[row] = ws[0] + ws[1] + ws[2] + ws[3];
}

// ---------------- fused GEMM ----------------
__global__ __launch_bounds__(GEMM_THREADS, 2)
void wq_gemm_kernel(const float* __restrict__ W,
                    const float* __restrict__ bias,
                    const float* __restrict__ scale,
                    const float* __restrict__ zero,
                    float* __restrict__ out)
{
    extern __shared__ char smem[];
    const uint32_t sb = s2u(smem);
    const int tid  = threadIdx.x;
    const int wid  = tid >> 5;
    const int lane = tid & 31;
    const int gid  = lane >> 2;
    const int tig  = lane & 3;
    const int wm   = wid & 1;        // 2 m-slabs of 64
    const int wn   = wid >> 1;       // 2 n-slabs of 32
    const int bn0 = blockIdx.x * BN;
    const int bm0 = blockIdx.y * BM;

    const __half* gA = g_Ah + (size_t)bm0 * K_TOTAL;
    const float*  gW = W + (size_t)bn0 * K_TOTAL;

    // staging maps
    const int a_row = tid >> 2;      // +32j, j<4
    const int a_c16 = tid & 3;
    const int w_row = tid >> 3;      // +16j, j<4 -> rows 0..63
    const int w_c16 = tid & 7;

    // quant task map: 2 tasks/thread; task = tid + 128*j
    //   row = task>>2 (0..63), g = (task>>1)&1, h = task&1
    const int q_row0 = tid >> 2;           // j=0 -> rows 0..31
    const int q_row1 = 32 + (tid >> 2);    // j=1 -> rows 32..63
    const int q_g = (tid >> 1) & 1;
    const int q_h = tid & 1;
    const float r0 = __fdiv_rn(1.0f, scale[bn0 + q_row0]);
    const float z0 = zero[bn0 + q_row0];
    const float r1 = __fdiv_rn(1.0f, scale[bn0 + q_row1]);
    const float z1 = zero[bn0 + q_row1];
    // word offset of quad0 within raw W row: k = g*16 + h*4
    const uint32_t q_koff = (uint32_t)((q_g * 16 + q_h * 4) * 4);   // bytes
    const uint32_t q_dst_off = (uint32_t)(q_g * 16 + q_h * 8);      // bytes in Bq row

    auto stage_tile = [&](int kt) {
        const int s = kt & (STAGES - 1);
        const uint32_t as = sb + s * STAGE_B;
        const uint32_t wsm = as + A_STAGE_B;
        const int k0 = kt * BK;
#pragma unroll
        for (int j = 0; j < 4; j++) {
            const int row = a_row + 32 * j;
            cpasync16(as + row * ROW_A + a_c16 * 16,
                      gA + (size_t)row * K_TOTAL + k0 + a_c16 * 8);
        }
#pragma unroll
        for (int j = 0; j < 4; j++) {
            const int row = w_row + 16 * j;
            cpasync16(wsm + row * ROW_W + w_c16 * 16,
                      gW + (size_t)row * K_TOTAL + k0 + w_c16 * 4);
        }
        asm volatile("cp.async.commit_group;" ::: "memory");
    };

    // quantize tile (stage s): raw fp32 W[s] -> permuted u8 Bq[s]
    auto quant_tile = [&](int s) {
        const uint32_t wsm = sb + s * STAGE_B + A_STAGE_B;
        const uint32_t qsm = wsm + W_STAGE_B;
#pragma unroll
        for (int j = 0; j < 2; j++) {
            const int row = j ? q_row1 : q_row0;
            const float rr = j ? r1 : r0;
            const float zz = j ? z1 : z0;
            const uint32_t base = wsm + row * ROW_W + q_koff;
            float4 qa = lds128f(base);        // k .. k+3
            float4 qb = lds128f(base + 32);   // k+8 .. k+11
            uint32_t i0 = quant1(qa.x, rr, zz), i1 = quant1(qa.y, rr, zz);
            uint32_t i2 = quant1(qa.z, rr, zz), i3 = quant1(qa.w, rr, zz);
            uint32_t i8 = quant1(qb.x, rr, zz), i9 = quant1(qb.y, rr, zz);
            uint32_t iA = quant1(qb.z, rr, zz), iB = quant1(qb.w, rr, zz);
            uint32_t d0 = i0 | (i1 << 8) | (i8 << 16) | (i9 << 24);
            uint32_t d1 = i2 | (i3 << 8) | (iA << 16) | (iB << 24);
            sts64(qsm + row * ROW_Q + q_dst_off, d0, d1);
        }
    };

    stage_tile(0);
    stage_tile(1);
    stage_tile(2);

    // fragment offsets
    const uint32_t a_frag = (uint32_t)((wm * 64 + (lane & 15)) * ROW_A + (lane >> 4) * 16);
    const uint32_t b_off  = (uint32_t)((wn * 32 + gid) * ROW_Q + tig * 4);

    float acc[4][4][4];
#pragma unroll
    for (int mt = 0; mt < 4; mt++)
#pragma unroll
        for (int nt = 0; nt < 4; nt++)
#pragma unroll
            for (int i = 0; i < 4; i++) acc[mt][nt][i] = 0.0f;

    // prologue: tiles 0,1 resident -> quant Bq[0]
    asm volatile("cp.async.wait_group 1;" ::: "memory");
    __syncthreads();
    quant_tile(0);

    for (int kt = 0; kt < NT; kt++) {
        const int s = kt & (STAGES - 1);
        const uint32_t as = sb + s * STAGE_B;
        const uint32_t qs = as + A_STAGE_B + W_STAGE_B;

        // RESIDENCY: tiles <= kt+1 complete after this wait (quant needs Wraw[kt+1]).
        if (kt + 3 <= NT) {
            asm volatile("cp.async.wait_group 1;" ::: "memory");
        } else {
            asm volatile("cp.async.wait_group 0;" ::: "memory");
        }
        __syncthreads();   // orders: prev-iter quant STS -> this-iter frag LDS; arrivals visible

        if (kt + 3 < NT) stage_tile(kt + 3);
        if (kt + 1 < NT) quant_tile((kt + 1) & (STAGES - 1));

#pragma unroll
        for (int ks = 0; ks < 2; ks++) {
            uint32_t af[4][4];
            uint32_t qd[4];
#pragma unroll
            for (int mt = 0; mt < 4; mt++)
                ldsm4(af[mt], as + a_frag + mt * (16 * ROW_A) + ks * 32);
#pragma unroll
            for (int nt = 0; nt < 4; nt++)
                qd[nt] = lds32(qs + b_off + nt * (8 * ROW_Q) + ks * 16);
#pragma unroll
            for (int nt = 0; nt < 4; nt++) {
                uint32_t bq[2];
                expand_q(qd[nt], bq);
#pragma unroll
                for (int mt = 0; mt < 4; mt++)
                    mma_f16(acc[mt][nt], af[mt], bq);
            }
        }
    }

    // Epilogue: out = scale*acc - scale*zero*S + bias
    float Sm[4][2];
#pragma unroll
    for (int mt = 0; mt < 4; mt++) {
        Sm[mt][0] = g_S[bm0 + wm * 64 + mt * 16 + gid];
        Sm[mt][1] = g_S[bm0 + wm * 64 + mt * 16 + gid + 8];
    }
#pragma unroll
    for (int nt = 0; nt < 4; nt++) {
        const int col = bn0 + wn * 32 + nt * 8 + tig * 2;
        const float2 sc = *(const float2*)(scale + col);
        const float2 zr = *(const float2*)(zero + col);
        const float2 bv = *(const float2*)(bias + col);
        const float sz0 = sc.x * zr.x, sz1 = sc.y * zr.y;
#pragma unroll
        for (int mt = 0; mt < 4; mt++) {
            const int row = bm0 + wm * 64 + mt * 16 + gid;
            float2 v0, v1;
            v0.x = sc.x * acc[mt][nt][0] - sz0 * Sm[mt][0] + bv.x;
            v0.y = sc.y * acc[mt][nt][1] - sz1 * Sm[mt][0] + bv.y;
            v1.x = sc.x * acc[mt][nt][2] - sz0 * Sm[mt][1] + bv.x;
            v1.y = sc.y * acc[mt][nt][3] - sz1 * Sm[mt][1] + bv.y;
            *(float2*)(out + (size_t)row * N_TOTAL + col) = v0;
            *(float2*)(out + (size_t)(row + 8) * N_TOTAL + col) = v1;
        }
    }
}

extern "C" void kernel_launch(void* const* d_in, const int* in_sizes, int n_in,
                              void* d_out, int out_size) {
    const float* input  = (const float*)d_in[0];
    const float* weight = (const float*)d_in[1];
    const float* bias   = (const float*)d_in[2];
    const float* scale  = (const float*)d_in[3];
    const float* zero   = (const float*)d_in[4];
    float* out = (float*)d_out;

    prepA_kernel<<<M_TOTAL, 128>>>(input);

    static bool attr_set = false;
    if (!attr_set) {
        cudaFuncSetAttribute(wq_gemm_kernel, cudaFuncAttributeMaxDynamicSharedMemorySize, SMEM_BYTES);
        attr_set = true;
    }
    dim3 grid(N_TOTAL / BN, M_TOTAL / BM);
    wq_gemm_kernel<<<grid, GEMM_THREADS, SMEM_BYTES>>>(weight, bias, scale, zero, out);
}

// round 15
// speedup vs baseline: 1.9054x; 1.9044x over previous
#include <cuda_runtime.h>
#include <cuda_fp16.h>
#include <cstdint>

// WQuantLinear factorized:
//   q = clip(round(w*(1/scale))+zero, 0, 15)   (exact small int)
//   out = scale[n]*(sum_k h(a)*q) - scale[n]*zero[n]*S[m] + bias[n]
// R14: prep (A->fp16+rowsums, W->permuted u8 q) + SPLIT-K x2 GEMM (688 small CTAs,
// 4 warps each, raw fp32 partials) + reduce kernel with fused affine epilogue.

constexpr int M_TOTAL = 256;
constexpr int N_TOTAL = 11008;
constexpr int K_TOTAL = 4096;

constexpr int BM = 128;
constexpr int BN = 64;
constexpr int BK = 32;
constexpr int KSPLIT = 2;
constexpr int K_HALF = K_TOTAL / KSPLIT;   // 2048
constexpr int NT2 = K_HALF / BK;           // 64 iterations per CTA
constexpr int GEMM_THREADS = 128;          // 4 warps: 2(m) x 2(n), 64x32 warp tiles
constexpr int STAGES = 4;

constexpr int ROW_A = 80;              // A: 64B fp16 + 16B pad (LDSM conflict-free)
constexpr int ROW_Q = 48;              // Bq: 32B u8 + 16B pad (12-word pitch, conflict-free)
constexpr int A_STAGE_B = BM * ROW_A;          // 10240
constexpr int B_STAGE_B = BN * ROW_Q;          // 3072
constexpr int STAGE_B = A_STAGE_B + B_STAGE_B; // 13312
constexpr int SMEM_BYTES = STAGES * STAGE_B;   // 53248

// ---- device scratch ----
__device__ __half  g_Ah[M_TOTAL * K_TOTAL];
__device__ float   g_S[M_TOTAL];
__device__ uint8_t g_Qu[(size_t)N_TOTAL * K_TOTAL];          // 45MB permuted u8 q
__device__ float   g_P[KSPLIT][(size_t)M_TOTAL * N_TOTAL];   // 22.5MB fp32 partials

__device__ __forceinline__ void mma_f16(float c[4], const uint32_t a[4], const uint32_t b[2]) {
    asm volatile(
        "mma.sync.aligned.m16n8k16.row.col.f32.f16.f16.f32 "
        "{%0,%1,%2,%3}, {%4,%5,%6,%7}, {%8,%9}, {%0,%1,%2,%3};"
        : "+f"(c[0]), "+f"(c[1]), "+f"(c[2]), "+f"(c[3])
        : "r"(a[0]), "r"(a[1]), "r"(a[2]), "r"(a[3]), "r"(b[0]), "r"(b[1]));
}
__device__ __forceinline__ void ldsm4(uint32_t r[4], uint32_t addr) {
    asm volatile("ldmatrix.sync.aligned.m8n8.x4.shared.b16 {%0,%1,%2,%3}, [%4];"
                 : "=r"(r[0]), "=r"(r[1]), "=r"(r[2]), "=r"(r[3]) : "r"(addr));
}
__device__ __forceinline__ uint32_t lds32(uint32_t addr) {
    uint32_t v;
    asm volatile("ld.shared.b32 %0, [%1];" : "=r"(v) : "r"(addr));
    return v;
}
__device__ __forceinline__ void cpasync16(uint32_t dst, const void* src) {
    asm volatile("cp.async.cg.shared.global [%0], [%1], 16;" :: "r"(dst), "l"(src) : "memory");
}
__device__ __forceinline__ uint32_t s2u(const void* p) {
    uint32_t a;
    asm("{ .reg .u64 t; cvta.to.shared.u64 t, %1; cvt.u32.u64 %0, t; }" : "=r"(a) : "l"(p));
    return a;
}
// qd bytes = [q(2t), q(2t+1), q(2t+8), q(2t+9)] -> exact fp16 pair regs
__device__ __forceinline__ void expand_q(uint32_t qd, uint32_t b[2]) {
    uint32_t p0, p1;
    asm("prmt.b32 %0, %1, %2, 0x4140;" : "=r"(p0) : "r"(qd), "r"(0x64646464u));
    asm("prmt.b32 %0, %1, %2, 0x4342;" : "=r"(p1) : "r"(qd), "r"(0x64646464u));
    asm("sub.rn.f16x2 %0, %1, %2;" : "=r"(b[0]) : "r"(p0), "r"(0x64006400u));
    asm("sub.rn.f16x2 %0, %1, %2;" : "=r"(b[1]) : "r"(p1), "r"(0x64006400u));
}

// ---------------- fused prep: W rows (0..N-1) + A rows (N..N+M-1) ----------------
__global__ __launch_bounds__(128) void prep_kernel(const float* __restrict__ A,
                                                   const float* __restrict__ W,
                                                   const float* __restrict__ scale,
                                                   const float* __restrict__ zero) {
    const int tid = threadIdx.x;
    if (blockIdx.x < (unsigned)N_TOTAL) {
        const int row = blockIdx.x;
        const float s = scale[row];
        const float z = zero[row];
        const float r = __fdiv_rn(1.0f, s);
        const float* src = W + (size_t)row * K_TOTAL;
        uint8_t* dst = g_Qu + (size_t)row * K_TOTAL;
#pragma unroll
        for (int half = 0; half < 2; half++) {
            const int g = tid + half * 128;        // 16-k group index
            const float* p = src + g * 16;
            uint32_t q[16];
#pragma unroll
            for (int j = 0; j < 4; j++) {
                float4 v = *(const float4*)(p + j * 4);
                q[j * 4 + 0] = (uint32_t)fminf(fmaxf(rintf(__fmul_rn(v.x, r)) + z, 0.0f), 15.0f);
                q[j * 4 + 1] = (uint32_t)fminf(fmaxf(rintf(__fmul_rn(v.y, r)) + z, 0.0f), 15.0f);
                q[j * 4 + 2] = (uint32_t)fminf(fmaxf(rintf(__fmul_rn(v.z, r)) + z, 0.0f), 15.0f);
                q[j * 4 + 3] = (uint32_t)fminf(fmaxf(rintf(__fmul_rn(v.w, r)) + z, 0.0f), 15.0f);
            }
            uint4 d;
            d.x = q[0] | (q[1] << 8) | (q[8]  << 16) | (q[9]  << 24);
            d.y = q[2] | (q[3] << 8) | (q[10] << 16) | (q[11] << 24);
            d.z = q[4] | (q[5] << 8) | (q[12] << 16) | (q[13] << 24);
            d.w = q[6] | (q[7] << 8) | (q[14] << 16) | (q[15] << 24);
            *(uint4*)(dst + g * 16) = d;
        }
    } else {
        const int row = blockIdx.x - N_TOTAL;
        const float* src = A + (size_t)row * K_TOTAL;
        __half* dst = g_Ah + (size_t)row * K_TOTAL;
        float s = 0.0f;
#pragma unroll
        for (int i = 0; i < K_TOTAL / (128 * 4); i++) {
            float4 v = *(const float4*)(src + (i * 128 + tid) * 4);
            __half h0 = __float2half_rn(v.x), h1 = __float2half_rn(v.y);
            __half h2 = __float2half_rn(v.z), h3 = __float2half_rn(v.w);
            __half2 p0 = __halves2half2(h0, h1), p1 = __halves2half2(h2, h3);
            *(uint2*)(dst + (i * 128 + tid) * 4) =
                make_uint2(*(uint32_t*)&p0, *(uint32_t*)&p1);
            s += __half2float(h0) + __half2float(h1) + __half2float(h2) + __half2float(h3);
        }
#pragma unroll
        for (int o = 16; o > 0; o >>= 1) s += __shfl_xor_sync(0xffffffffu, s, o);
        __shared__ float ws[4];
        if ((tid & 31) == 0) ws[tid >> 5] = s;
        __syncthreads();
        if (tid == 0) g_S[row] = ws[0] + ws[1] + ws[2] + ws[3];
    }
}

// ---------------- split-K GEMM: partial acc -> g_P[kh] ----------------
__global__ __launch_bounds__(GEMM_THREADS, 4)
void wq_gemm_kernel(float* __restrict__ dummy)
{
    extern __shared__ char smem[];
    const uint32_t sb = s2u(smem);
    const int tid  = threadIdx.x;
    const int wid  = tid >> 5;
    const int lane = tid & 31;
    const int gid  = lane >> 2;
    const int tig  = lane & 3;
    const int wm   = wid & 1;        // 2 m-slabs of 64
    const int wn   = wid >> 1;       // 2 n-slabs of 32
    const int bn0 = blockIdx.x * BN;
    const int bm0 = blockIdx.y * BM;
    const int kh  = blockIdx.z;      // K-split half
    const int kbase = kh * K_HALF;

    const __half*  gA = g_Ah + (size_t)bm0 * K_TOTAL + kbase;
    const uint8_t* gQ = g_Qu + (size_t)bn0 * K_TOTAL + kbase;

    // staging: A 512 chunks (4/thread); B 128 chunks (1 for tid<128... 64 rows x 2)
    const int a_row = tid >> 2;
    const int a_c16 = tid & 3;
    const int b_row = tid >> 1;      // 0..63
    const int b_c16 = tid & 1;

    auto stage_tile = [&](int kt) {
        const int s = kt & (STAGES - 1);
        const uint32_t as = sb + s * STAGE_B;
        const uint32_t bs = as + A_STAGE_B;
        const int k0 = kt * BK;
#pragma unroll
        for (int j = 0; j < 4; j++) {
            const int row = a_row + 32 * j;
            cpasync16(as + row * ROW_A + a_c16 * 16,
                      gA + (size_t)row * K_TOTAL + k0 + a_c16 * 8);
        }
        cpasync16(bs + b_row * ROW_Q + b_c16 * 16,
                  gQ + (size_t)b_row * K_TOTAL + k0 + b_c16 * 16);
        asm volatile("cp.async.commit_group;" ::: "memory");
    };

    stage_tile(0);
    stage_tile(1);
    stage_tile(2);

    const uint32_t a_frag = (uint32_t)((wm * 64 + (lane & 15)) * ROW_A + (lane >> 4) * 16);
    const uint32_t b_off  = (uint32_t)((wn * 32 + gid) * ROW_Q + tig * 4);

    float acc[4][4][4];
#pragma unroll
    for (int mt = 0; mt < 4; mt++)
#pragma unroll
        for (int nt = 0; nt < 4; nt++)
#pragma unroll
            for (int i = 0; i < 4; i++) acc[mt][nt][i] = 0.0f;

    for (int kt = 0; kt < NT2; kt++) {
        const int s = kt & (STAGES - 1);
        const uint32_t as = sb + s * STAGE_B;
        const uint32_t qs = as + A_STAGE_B;

        // Need tile kt resident (no cross-tile frag prefetch in this variant).
        // Committed groups so far: min(kt+3, NT2). Allowed outstanding:
        if (kt <= NT2 - 3) {
            asm volatile("cp.async.wait_group 2;" ::: "memory");
        } else if (kt == NT2 - 2) {
            asm volatile("cp.async.wait_group 1;" ::: "memory");
        } else {
            asm volatile("cp.async.wait_group 0;" ::: "memory");
        }
        __syncthreads();

        if (kt + 3 < NT2) stage_tile(kt + 3);

#pragma unroll
        for (int ks = 0; ks < 2; ks++) {
            uint32_t af[4][4];
            uint32_t qd[4];
#pragma unroll
            for (int mt = 0; mt < 4; mt++)
                ldsm4(af[mt], as + a_frag + mt * (16 * ROW_A) + ks * 32);
#pragma unroll
            for (int nt = 0; nt < 4; nt++)
                qd[nt] = lds32(qs + b_off + nt * (8 * ROW_Q) + ks * 16);
#pragma unroll
            for (int nt = 0; nt < 4; nt++) {
                uint32_t bq[2];
                expand_q(qd[nt], bq);
#pragma unroll
                for (int mt = 0; mt < 4; mt++)
                    mma_f16(acc[mt][nt], af[mt], bq);
            }
        }
    }

    // store raw partials
    float* po = g_P[kh];
#pragma unroll
    for (int nt = 0; nt < 4; nt++) {
        const int col = bn0 + wn * 32 + nt * 8 + tig * 2;
#pragma unroll
        for (int mt = 0; mt < 4; mt++) {
            const int row = bm0 + wm * 64 + mt * 16 + gid;
            *(float2*)(po + (size_t)row * N_TOTAL + col) =
                make_float2(acc[mt][nt][0], acc[mt][nt][1]);
            *(float2*)(po + (size_t)(row + 8) * N_TOTAL + col) =
                make_float2(acc[mt][nt][2], acc[mt][nt][3]);
        }
    }
    (void)dummy;
}

// ---------------- reduce: sum halves + affine epilogue ----------------
__global__ __launch_bounds__(128) void reduce_kernel(const float* __restrict__ bias,
                                                     const float* __restrict__ scale,
                                                     const float* __restrict__ zero,
                                                     float* __restrict__ out)
{
    const int m = blockIdx.y;
    const int n = (blockIdx.x * 128 + threadIdx.x) * 2;   // 43 blocks * 128 thr * 2 = 11008
    const size_t off = (size_t)m * N_TOTAL + n;
    const float Sm = g_S[m];
    float2 p0 = *(const float2*)(&g_P[0][off]);
    float2 p1 = *(const float2*)(&g_P[1][off]);
    const float2 sc = *(const float2*)(scale + n);
    const float2 zr = *(const float2*)(zero + n);
    const float2 bv = *(const float2*)(bias + n);
    float2 v;
    v.x = sc.x * (p0.x + p1.x) - sc.x * zr.x * Sm + bv.x;
    v.y = sc.y * (p0.y + p1.y) - sc.y * zr.y * Sm + bv.y;
    *(float2*)(out + off) = v;
}

extern "C" void kernel_launch(void* const* d_in, const int* in_sizes, int n_in,
                              void* d_out, int out_size) {
    const float* input  = (const float*)d_in[0];
    const float* weight = (const float*)d_in[1];
    const float* bias   = (const float*)d_in[2];
    const float* scale  = (const float*)d_in[3];
    const float* zero   = (const float*)d_in[4];
    float* out = (float*)d_out;

    prep_kernel<<<N_TOTAL + M_TOTAL, 128>>>(input, weight, scale, zero);

    static bool attr_set = false;
    if (!attr_set) {
        cudaFuncSetAttribute(wq_gemm_kernel, cudaFuncAttributeMaxDynamicSharedMemorySize, SMEM_BYTES);
        attr_set = true;
    }
    dim3 grid(N_TOTAL / BN, M_TOTAL / BM, KSPLIT);   // 172 x 2 x 2 = 688 CTAs
    wq_gemm_kernel<<<grid, GEMM_THREADS, SMEM_BYTES>>>(out);

    dim3 rgrid(N_TOTAL / 256, M_TOTAL);              // 43 x 256
    reduce_kernel<<<rgrid, 128>>>(bias, scale, zero, out);
}